// round 14
// baseline (speedup 1.0000x reference)
#include <cuda_runtime.h>
#include <cuda_fp16.h>
#include <cstdint>

#define B_ 32
#define H_ 128
#define W_ 128
#define N_ 1024
#define K_ 49152
#define ROWS_ 384
#define SLABS_ 37
#define NTB_ 128

__device__ float    g_gy  [H_*N_];
__device__ uint16_t g_gxnh[W_*N_];   // gx*norm as fp16
__device__ uint16_t g_xh  [B_*K_];

// smem layout (bytes)
#define SM_GY  0                     // 11 rows * 512 = 5632
#define SM_A   5632                  // 2 bufs * 4 chunks * 1568 = 12544
#define SM_B   (5632+12544)          // 2 bufs * 64 rows * 272 = 69632
#define BB_    34816                 // one B buffer
#define SMEM_TOTAL (SM_B + 2*BB_)    // 87808

__device__ __forceinline__ uint32_t s2u(const void* p){
    return (uint32_t)__cvta_generic_to_shared(p);
}
__device__ __forceinline__ uint32_t packh2(float a, float b){
    __half2 h = __floats2half2_rn(a, b);
    return *(uint32_t*)&h;
}
__device__ __forceinline__ void ldsm_x4(uint32_t* r, uint32_t a){
    asm volatile("ldmatrix.sync.aligned.m8n8.x4.shared.b16 {%0,%1,%2,%3}, [%4];"
      : "=r"(r[0]),"=r"(r[1]),"=r"(r[2]),"=r"(r[3]) : "r"(a));
}
__device__ __forceinline__ void ldsm_x4t(uint32_t* r, uint32_t a){
    asm volatile("ldmatrix.sync.aligned.m8n8.x4.trans.shared.b16 {%0,%1,%2,%3}, [%4];"
      : "=r"(r[0]),"=r"(r[1]),"=r"(r[2]),"=r"(r[3]) : "r"(a));
}
__device__ __forceinline__ void mma_f16(float* c, const uint32_t* a, uint32_t b0, uint32_t b1){
    asm volatile("mma.sync.aligned.m16n8k16.row.col.f32.f16.f16.f32 "
      "{%0,%1,%2,%3}, {%4,%5,%6,%7}, {%8,%9}, {%0,%1,%2,%3};"
      : "+f"(c[0]),"+f"(c[1]),"+f"(c[2]),"+f"(c[3])
      : "r"(a[0]),"r"(a[1]),"r"(a[2]),"r"(a[3]),"r"(b0),"r"(b1));
}

// ---- kernel 1: prep = tables (blocks 0..1023, + zero out) + x->fp16 (1024..4095) ----
__global__ void prep(const float* __restrict__ x,
                     const float* __restrict__ mu_x, const float* __restrict__ mu_y,
                     const float* __restrict__ sg_x, const float* __restrict__ sg_y,
                     float* __restrict__ out)
{
    if (blockIdx.x < 1024){
        __shared__ float red[8];
        int n = blockIdx.x, i = threadIdx.x;
        if (i < 8)
            ((float4*)out)[blockIdx.x*8 + i] = make_float4(0.f,0.f,0.f,0.f);
        float mx = mu_x[n], my = mu_y[n], isx = 1.f/sg_x[n], isy = 1.f/sg_y[n];
        float g = (float)i*(1.f/127.f);
        float tx = (g-mx)*isx, ty = (g-my)*isy;
        float vx = expf(-0.5f*tx*tx), vy = expf(-0.5f*ty*ty);
        float sx2 = vx*vx, sy2 = vy*vy;
#pragma unroll
        for (int o=16;o;o>>=1){ sx2 += __shfl_xor_sync(~0u,sx2,o); sy2 += __shfl_xor_sync(~0u,sy2,o); }
        if ((i&31)==0){ red[i>>5]=sx2; red[4+(i>>5)]=sy2; }
        __syncthreads();
        sx2 = red[0]+red[1]+red[2]+red[3]; sy2 = red[4]+red[5]+red[6]+red[7];
        float nrm = sqrtf((float)(H_*W_)/(sx2*sy2));   // C cancels
        __half hx = __float2half_rn(vx*nrm);
        g_gxnh[i*N_+n] = *(uint16_t*)&hx;
        g_gy  [i*N_+n] = vy;
    } else {
        int i = (blockIdx.x-1024)*128 + threadIdx.x;
        float4 v = ((const float4*)x)[i];
        __half2 h0 = __floats2half2_rn(v.x,v.y), h1 = __floats2half2_rn(v.z,v.w);
        ((uint2*)g_xh)[i] = make_uint2(*(uint32_t*)&h0, *(uint32_t*)&h1);
    }
}

// ---- kernel 2: group-staged masked fp16 MMA GEMM + REDG epilogue ----
__global__ __launch_bounds__(256,2) void main_kernel(const float* __restrict__ wgt,
                                                     float* __restrict__ out)
{
    extern __shared__ char smem[];
    float* gy_s = (float*)(smem + SM_GY);

    const int t = threadIdx.x, lane = t&31, w = t>>5;
    const int slab = blockIdx.x, nbase = blockIdx.y*NTB_;
    const int r0 = slab*ROWS_/SLABS_, rows = (slab+1)*ROWS_/SLABS_ - r0;
    const int ngroups = rows*2;                  // group = 4 chunks = 64 k
    const int kbase = r0*W_;

    // gy rows -> smem (f32, stride 128)
    for (int i = t; i < rows*32; i += 256){
        int rr = i>>5, p = (i&31)*4, h = (r0+rr)&(H_-1);
        *(float4*)(gy_s + rr*NTB_ + p) = *(const float4*)(g_gy + h*N_ + nbase + p);
    }

    // gxn -> registers: 16 wcols x 4 n fp16 per thread
    uint2 gxr[16];
#pragma unroll
    for (int p = 0; p < 16; ++p){
        int wcol = (p>>3)*64 + w*8 + (p&7);
        gxr[p] = *(const uint2*)(g_gxnh + (size_t)wcol*N_ + nbase + lane*4);
    }

    const int bA = t>>3, hA = t&7;               // A staging role
    const int mat = lane>>3, rowin = lane&7;
    const uint32_t aOff = (uint32_t)(((mat&1)*8 + rowin)*48 + (mat>>1)*16);
    const uint32_t bOff = (uint32_t)(((mat&1)*8 + rowin)*272 + w*32 + (mat>>1)*16);
    const uint32_t smA = s2u(smem + SM_A), smB = s2u(smem + SM_B);

    float4 ws[2][2];     // weight LDG ring: 2 slots x 2 rows
#define LDWS(cp,s) do { int gt_ = ((cp)>>2)+1; if (gt_ < ngroups){ \
    int kg_ = kbase + gt_*64 + w*8 + 2*((cp)&3); \
    const float* p_ = wgt + (size_t)kg_*N_ + nbase + lane*4; \
    ws[s][0] = *(const float4*)p_; ws[s][1] = *(const float4*)(p_ + N_); } } while(0)

    __syncthreads();     // gy_s ready

    // ---- prologue: stage group 0 (A + B) synchronously ----
    {
        uint4 av = *(const uint4*)(g_xh + (size_t)bA*K_ + kbase + hA*8);
        *(uint4*)(smem + SM_A + (hA>>1)*1568 + bA*48 + (hA&1)*16) = av;
        float4 gy0 = *(const float4*)(gy_s + lane*4);
#pragma unroll
        for (int j = 0; j < 8; ++j){
            int l = w*8 + j;                     // buffer row = slab k (group 0)
            const float* p_ = wgt + (size_t)(kbase + l)*N_ + nbase + lane*4;
            float4 wv = *(const float4*)p_;
            float2 gA = __half22float2(*(__half2*)&gxr[j].x);
            float2 gB = __half22float2(*(__half2*)&gxr[j].y);
            uint2 st = make_uint2(packh2(wv.x*gA.x*gy0.x, wv.y*gA.y*gy0.y),
                                  packh2(wv.z*gB.x*gy0.z, wv.w*gB.y*gy0.w));
            *(uint2*)(smem + SM_B + l*272 + lane*8) = st;
        }
    }
    LDWS(0,0); LDWS(1,1);

    float acc[2][2][4];
#pragma unroll
    for (int a=0;a<2;a++)
#pragma unroll
      for (int b=0;b<2;b++)
#pragma unroll
        for (int p=0;p<4;p++) acc[a][b][p] = 0.f;

    __syncthreads();     // group 0 buffers ready

    for (int G = 0; G < ngroups; ++G){
        const int gb = G & 1, gt = G + 1, tb = gt & 1;
        const bool more = (gt < ngroups);
        uint4 av;
        float4 gyt;
        if (more){
            av  = *(const uint4*)(g_xh + (size_t)bA*K_ + kbase + gt*64 + hA*8);
            gyt = *(const float4*)(gy_s + (gt>>1)*NTB_ + lane*4);
        }
#pragma unroll
        for (int cc = 0; cc < 4; ++cc){
            const int c = G*4 + cc;
            uint32_t A0[4], A1[4], Bv[4];
            const uint32_t aBase = smA + gb*12544/2*0 + gb*6272 + cc*1568 + aOff;
            ldsm_x4 (A0, aBase);
            ldsm_x4 (A1, aBase + 768);
            ldsm_x4t(Bv, smB + gb*BB_ + cc*16*272 + bOff);
            if (more){       // convert pair (2cc,2cc+1) of group G+1 from slot c&1
                const int l0 = 2*cc, pbase = tb*8 + l0;
#pragma unroll
                for (int j = 0; j < 2; ++j){
                    float4 wv = ws[c&1][j];
                    float2 gA = __half22float2(*(__half2*)&gxr[pbase+j].x);
                    float2 gB = __half22float2(*(__half2*)&gxr[pbase+j].y);
                    uint2 st = make_uint2(packh2(wv.x*gA.x*gyt.x, wv.y*gA.y*gyt.y),
                                          packh2(wv.z*gB.x*gyt.z, wv.w*gB.y*gyt.w));
                    *(uint2*)(smem + SM_B + tb*BB_ + (w*8 + l0 + j)*272 + lane*8) = st;
                }
            }
            LDWS(c+2, c&1);
            mma_f16(acc[0][0], A0, Bv[0], Bv[1]);
            mma_f16(acc[0][1], A0, Bv[2], Bv[3]);
            mma_f16(acc[1][0], A1, Bv[0], Bv[1]);
            mma_f16(acc[1][1], A1, Bv[2], Bv[3]);
        }
        if (more)
            *(uint4*)(smem + SM_A + tb*6272 + (hA>>1)*1568 + bA*48 + (hA&1)*16) = av;
        __syncthreads();
    }
#undef LDWS

    // epilogue: REDG atomics into out (validated mapping)
    const int grp = lane>>2, tg = lane&3;
#pragma unroll
    for (int mt = 0; mt < 2; ++mt)
#pragma unroll
        for (int nb = 0; nb < 2; ++nb){
            int b = mt*16 + grp;
            int n = nbase + w*16 + nb*8 + tg*2;
            atomicAdd(out + (size_t)b*N_ + n,       acc[mt][nb][0]);
            atomicAdd(out + (size_t)b*N_ + n + 1,   acc[mt][nb][1]);
            atomicAdd(out + (size_t)(b+8)*N_ + n,   acc[mt][nb][2]);
            atomicAdd(out + (size_t)(b+8)*N_ + n+1, acc[mt][nb][3]);
        }
}

extern "C" void kernel_launch(void* const* d_in, const int* in_sizes, int n_in,
                              void* d_out, int out_size)
{
    const float* x   = (const float*)d_in[0];
    const float* mux = (const float*)d_in[1];
    const float* muy = (const float*)d_in[2];
    const float* sx  = (const float*)d_in[3];
    const float* sy  = (const float*)d_in[4];
    const float* wgt = (const float*)d_in[5];
    cudaFuncSetAttribute(main_kernel, cudaFuncAttributeMaxDynamicSharedMemorySize, SMEM_TOTAL);
    prep<<<4096, 128>>>(x, mux, muy, sx, sy, (float*)d_out);
    main_kernel<<<dim3(SLABS_, 8), 256, SMEM_TOTAL>>>(wgt, (float*)d_out);
}

// round 16
// speedup vs baseline: 1.0277x; 1.0277x over previous
#include <cuda_runtime.h>
#include <cuda_fp16.h>
#include <cstdint>

#define B_ 32
#define H_ 128
#define W_ 128
#define N_ 1024
#define K_ 49152
#define ROWS_ 384
#define SLABS_ 37
#define NTB_ 128
#define RING 8                        // cp.async weight ring depth (chunks)

__device__ float    g_gy  [H_*N_];
__device__ uint16_t g_gxnh[W_*N_];    // gx*norm as fp16
__device__ uint16_t g_xh  [B_*K_];

// smem layout (bytes)
#define SM_GY  0                      // 11 rows * 512 = 5632
#define ACS    1568
#define ABUF   (8*ACS)                // 12544
#define SM_A   5632                   // 2 bufs
#define SM_B   (5632 + 2*ABUF)        // 8 warps * 2 bufs * 768 = 12288
#define SM_RAW (SM_B + 12288)         // 8 warps * RING * 1024 = 65536
#define SMEM_TOTAL (SM_RAW + 8*RING*1024)   // 108544

__device__ __forceinline__ uint32_t s2u(const void* p){
    return (uint32_t)__cvta_generic_to_shared(p);
}
__device__ __forceinline__ uint32_t packh2(float a, float b){
    __half2 h = __floats2half2_rn(a, b);
    return *(uint32_t*)&h;
}
__device__ __forceinline__ void ldsm_x4(uint32_t* r, uint32_t a){
    asm volatile("ldmatrix.sync.aligned.m8n8.x4.shared.b16 {%0,%1,%2,%3}, [%4];"
      : "=r"(r[0]),"=r"(r[1]),"=r"(r[2]),"=r"(r[3]) : "r"(a));
}
__device__ __forceinline__ void ldsm_x4t(uint32_t* r, uint32_t a){
    asm volatile("ldmatrix.sync.aligned.m8n8.x4.trans.shared.b16 {%0,%1,%2,%3}, [%4];"
      : "=r"(r[0]),"=r"(r[1]),"=r"(r[2]),"=r"(r[3]) : "r"(a));
}
__device__ __forceinline__ void mma_f16(float* c, const uint32_t* a, uint32_t b0, uint32_t b1){
    asm volatile("mma.sync.aligned.m16n8k16.row.col.f32.f16.f16.f32 "
      "{%0,%1,%2,%3}, {%4,%5,%6,%7}, {%8,%9}, {%0,%1,%2,%3};"
      : "+f"(c[0]),"+f"(c[1]),"+f"(c[2]),"+f"(c[3])
      : "r"(a[0]),"r"(a[1]),"r"(a[2]),"r"(a[3]),"r"(b0),"r"(b1));
}

// ---- kernel 1: prep = tables (blocks 0..1023, + zero out) + x->fp16 (1024..4095) ----
__global__ void prep(const float* __restrict__ x,
                     const float* __restrict__ mu_x, const float* __restrict__ mu_y,
                     const float* __restrict__ sg_x, const float* __restrict__ sg_y,
                     float* __restrict__ out)
{
    if (blockIdx.x < 1024){
        __shared__ float red[8];
        int n = blockIdx.x, i = threadIdx.x;
        if (i < 8)
            ((float4*)out)[blockIdx.x*8 + i] = make_float4(0.f,0.f,0.f,0.f);
        float mx = mu_x[n], my = mu_y[n], isx = 1.f/sg_x[n], isy = 1.f/sg_y[n];
        float g = (float)i*(1.f/127.f);
        float tx = (g-mx)*isx, ty = (g-my)*isy;
        float vx = expf(-0.5f*tx*tx), vy = expf(-0.5f*ty*ty);
        float sx2 = vx*vx, sy2 = vy*vy;
#pragma unroll
        for (int o=16;o;o>>=1){ sx2 += __shfl_xor_sync(~0u,sx2,o); sy2 += __shfl_xor_sync(~0u,sy2,o); }
        if ((i&31)==0){ red[i>>5]=sx2; red[4+(i>>5)]=sy2; }
        __syncthreads();
        sx2 = red[0]+red[1]+red[2]+red[3]; sy2 = red[4]+red[5]+red[6]+red[7];
        float nrm = sqrtf((float)(H_*W_)/(sx2*sy2));   // C cancels
        __half hx = __float2half_rn(vx*nrm);
        g_gxnh[i*N_+n] = *(uint16_t*)&hx;
        g_gy  [i*N_+n] = vy;
    } else {
        int i = (blockIdx.x-1024)*128 + threadIdx.x;
        float4 v = ((const float4*)x)[i];
        __half2 h0 = __floats2half2_rn(v.x,v.y), h1 = __floats2half2_rn(v.z,v.w);
        ((uint2*)g_xh)[i] = make_uint2(*(uint32_t*)&h0, *(uint32_t*)&h1);
    }
}

// ---- kernel 2: cp.async-pipelined masked fp16 MMA GEMM + REDG epilogue ----
__global__ __launch_bounds__(256,2) void main_kernel(const float* __restrict__ wgt,
                                                     float* __restrict__ out)
{
    extern __shared__ char smem[];
    float* gy_s = (float*)(smem + SM_GY);

    const int t = threadIdx.x, lane = t&31, w = t>>5;
    const int slab = blockIdx.x, nbase = blockIdx.y*NTB_;
    const int r0 = slab*ROWS_/SLABS_, rows = (slab+1)*ROWS_/SLABS_ - r0;
    const int nch = rows*8, kbase = r0*W_;

    // gy rows -> smem (f32, stride 128)
    for (int i = t; i < rows*32; i += 256){
        int rr = i>>5, p = (i&31)*4, h = (r0+rr)&(H_-1);
        *(float4*)(gy_s + rr*NTB_ + p) = *(const float4*)(g_gy + h*N_ + nbase + p);
    }

    const int kq = lane>>2, q = lane&3;
    const int nq = w*16 + q*4;
    const float* wbase = wgt + (size_t)nbase + nq;

    // gxn -> fp16 registers: wcol = cc*16 + kq + h*8, 4 n each
    uint2 gxr[16];
#pragma unroll
    for (int cc = 0; cc < 8; ++cc)
#pragma unroll
        for (int h = 0; h < 2; ++h)
            gxr[2*cc+h] = *(const uint2*)(g_gxnh + (size_t)(cc*16+kq+h*8)*N_ + nbase + nq);

    const int bA = t>>3, hA = t&7;
    const int mat = lane>>3, rowin = lane&7;
    const uint32_t aOff = (uint32_t)(((mat&1)*8 + rowin)*48 + (mat>>1)*16);
    const uint32_t bOff = aOff;
    const uint32_t smA = s2u(smem + SM_A);
    const uint32_t smBw = s2u(smem + SM_B) + w*1536;
    char* bwp  = smem + SM_B + w*1536;
    char* rawg = smem + SM_RAW + w*(RING*1024) + lane*32;   // generic read ptr
    const uint32_t rawS = s2u(rawg);                        // shared addr for cp.async dst

// issue cp.async for chunk c (2x16B per lane) + commit group (always commit)
#define CPA(c) do { \
    if ((c) < nch){ \
        const float* s0_ = wbase + (size_t)(kbase + (c)*16 + kq)*N_; \
        uint32_t d0_ = rawS + ((c)&(RING-1))*1024; \
        asm volatile("cp.async.cg.shared.global [%0], [%1], 16;" :: "r"(d0_), "l"(s0_) : "memory"); \
        asm volatile("cp.async.cg.shared.global [%0], [%1], 16;" :: "r"(d0_+16), "l"(s0_+8*N_) : "memory"); \
    } \
    asm volatile("cp.async.commit_group;" ::: "memory"); } while(0)

    // prologue: A row 0 (BOTH halves), weight chunks 0..RING-1 in flight
    {
        const uint16_t* xp = g_xh + (size_t)bA*K_ + kbase;
        uint4 a0 = *(const uint4*)(xp + hA*8);
        uint4 a1 = *(const uint4*)(xp + 64 + hA*8);
        *(uint4*)(smem + SM_A + (hA>>1)*ACS + bA*48 + (hA&1)*16)     = a0;
        *(uint4*)(smem + SM_A + (4+(hA>>1))*ACS + bA*48 + (hA&1)*16) = a1;
    }
#pragma unroll
    for (int c = 0; c < RING; ++c) CPA(c);

    float acc[2][2][4];
#pragma unroll
    for (int a=0;a<2;a++)
#pragma unroll
      for (int b=0;b<2;b++)
#pragma unroll
        for (int p=0;p<4;p++) acc[a][b][p] = 0.f;

    __syncthreads();   // gy_s + A buf0 ready

    int ab = 0;
    for (int g = 0; g < rows; ++g){
        const bool more = (g+1 < rows);
        uint4 av0, av1;
        if (more){
            const uint16_t* xp = g_xh + (size_t)bA*K_ + kbase + (g+1)*W_;
            av0 = *(const uint4*)(xp + hA*8);
            av1 = *(const uint4*)(xp + 64 + hA*8);
        }
        const float4 gyv = *(const float4*)(gy_s + g*NTB_ + nq);

#pragma unroll
        for (int cc = 0; cc < 8; ++cc){
            const int c = g*8 + cc, bb = c&1;
            // wait for chunk c's weights (keep RING-1 groups in flight)
            asm volatile("cp.async.wait_group %0;" :: "n"(RING-1) : "memory");
            const char* rp = rawg + (c&(RING-1))*1024;
            float4 w0 = *(const float4*)(rp);
            float4 w1 = *(const float4*)(rp + 16);
            // masked fp16 convert -> warp-private B tile
            float2 gA0 = __half22float2(*(__half2*)&gxr[2*cc].x);
            float2 gB0 = __half22float2(*(__half2*)&gxr[2*cc].y);
            float2 gA1 = __half22float2(*(__half2*)&gxr[2*cc+1].x);
            float2 gB1 = __half22float2(*(__half2*)&gxr[2*cc+1].y);
            uint2 lo = make_uint2(packh2(w0.x*gA0.x*gyv.x, w0.y*gA0.y*gyv.y),
                                  packh2(w0.z*gB0.x*gyv.z, w0.w*gB0.y*gyv.w));
            uint2 hi = make_uint2(packh2(w1.x*gA1.x*gyv.x, w1.y*gA1.y*gyv.y),
                                  packh2(w1.z*gB1.x*gyv.z, w1.w*gB1.y*gyv.w));
            *(uint2*)(bwp + bb*768 + kq*48 + q*8)     = lo;
            *(uint2*)(bwp + bb*768 + (kq+8)*48 + q*8) = hi;
            __syncwarp();

            uint32_t A0[4], A1[4], Bv[4];
            const uint32_t aBase = smA + ab*ABUF + cc*ACS + aOff;
            ldsm_x4 (A0, aBase);
            ldsm_x4 (A1, aBase + 768);
            ldsm_x4t(Bv, smBw + bb*768 + bOff);
            CPA(c + RING);            // refill slot (data read ~600cyc before this can land)
            mma_f16(acc[0][0], A0, Bv[0], Bv[1]);
            mma_f16(acc[0][1], A0, Bv[2], Bv[3]);
            mma_f16(acc[1][0], A1, Bv[0], Bv[1]);
            mma_f16(acc[1][1], A1, Bv[2], Bv[3]);
        }
        if (more){
            char* ad = smem + SM_A + (ab^1)*ABUF;
            *(uint4*)(ad + (hA>>1)*ACS + bA*48 + (hA&1)*16)     = av0;
            *(uint4*)(ad + (4+(hA>>1))*ACS + bA*48 + (hA&1)*16) = av1;
        }
        __syncthreads();
        ab ^= 1;
    }
#undef CPA

    // epilogue: REDG atomics into out (validated mapping)
    const int grp = lane>>2, tg = lane&3;
#pragma unroll
    for (int mt = 0; mt < 2; ++mt)
#pragma unroll
        for (int nb = 0; nb < 2; ++nb){
            int b = mt*16 + grp;
            int n = nbase + w*16 + nb*8 + tg*2;
            atomicAdd(out + (size_t)b*N_ + n,       acc[mt][nb][0]);
            atomicAdd(out + (size_t)b*N_ + n + 1,   acc[mt][nb][1]);
            atomicAdd(out + (size_t)(b+8)*N_ + n,   acc[mt][nb][2]);
            atomicAdd(out + (size_t)(b+8)*N_ + n+1, acc[mt][nb][3]);
        }
}

extern "C" void kernel_launch(void* const* d_in, const int* in_sizes, int n_in,
                              void* d_out, int out_size)
{
    const float* x   = (const float*)d_in[0];
    const float* mux = (const float*)d_in[1];
    const float* muy = (const float*)d_in[2];
    const float* sx  = (const float*)d_in[3];
    const float* sy  = (const float*)d_in[4];
    const float* wgt = (const float*)d_in[5];
    cudaFuncSetAttribute(main_kernel, cudaFuncAttributeMaxDynamicSharedMemorySize, SMEM_TOTAL);
    prep<<<4096, 128>>>(x, mux, muy, sx, sy, (float*)d_out);
    main_kernel<<<dim3(SLABS_, 8), 256, SMEM_TOTAL>>>(wgt, (float*)d_out);
}